// round 8
// baseline (speedup 1.0000x reference)
#include <cuda_runtime.h>
#include <cuda_fp16.h>
#include <cstdint>

#define BSZ  256
#define FDIM 128
#define DDIM 512
#define HH   8
#define HD   64
#define KTOP 64
#define MTOT (BSZ * FDIM)            // 32768
#define LOSCALE 2048.0f
#define INVLOSCALE (1.0f / 2048.0f)

// ---------------- scratch (device globals: allocation-free) ----------------
__device__ float g_qkv[(size_t)3 * MTOT * DDIM];   // q,k,v in (B,F,D) plain layout
__device__ float g_pv[BSZ];
__device__ __half g_xhi[(size_t)MTOT * DDIM];
__device__ __half g_xlo[(size_t)MTOT * DDIM];      // scaled by 2048
__device__ __half g_ahi[(size_t)MTOT * DDIM];      // attn out hi (written by attn_kernel)
__device__ __half g_alo[(size_t)MTOT * DDIM];      // attn out lo (scaled by 2048)
__device__ __half g_wthi[(size_t)4 * DDIM * DDIM]; // W^T (n,k) for q,k,v,o
__device__ __half g_wtlo[(size_t)4 * DDIM * DDIM]; // scaled by 2048

// ---------------- helpers ----------------
typedef unsigned long long u64c;

__device__ __forceinline__ uint32_t smem_u32(const void* p) {
    uint32_t a;
    asm("{ .reg .u64 t; cvta.to.shared.u64 t, %1; cvt.u32.u64 %0, t; }" : "=r"(a) : "l"(p));
    return a;
}
__device__ __forceinline__ void cp_async16(uint32_t dst, const void* src) {
    asm volatile("cp.async.cg.shared.global [%0], [%1], 16;" :: "r"(dst), "l"(src) : "memory");
}
__device__ __forceinline__ void cp_commit() {
    asm volatile("cp.async.commit_group;" ::: "memory");
}
template<int N>
__device__ __forceinline__ void cp_wait() {
    asm volatile("cp.async.wait_group %0;" :: "n"(N) : "memory");
}
__device__ __forceinline__ void ldm_x4(uint32_t* r, uint32_t addr) {
    asm volatile("ldmatrix.sync.aligned.m8n8.x4.shared.b16 {%0,%1,%2,%3}, [%4];"
                 : "=r"(r[0]), "=r"(r[1]), "=r"(r[2]), "=r"(r[3]) : "r"(addr));
}
__device__ __forceinline__ void mma16816(float* c, const uint32_t* a, uint32_t b0, uint32_t b1) {
    asm volatile(
        "mma.sync.aligned.m16n8k16.row.col.f32.f16.f16.f32 "
        "{%0,%1,%2,%3}, {%4,%5,%6,%7}, {%8,%9}, {%0,%1,%2,%3};"
        : "+f"(c[0]), "+f"(c[1]), "+f"(c[2]), "+f"(c[3])
        : "r"(a[0]), "r"(a[1]), "r"(a[2]), "r"(a[3]), "r"(b0), "r"(b1));
}
// packed f32x2 ops (sm_100+ base ISA)
__device__ __forceinline__ u64c pk2(float a, float b) {
    u64c r; asm("mov.b64 %0, {%1, %2};" : "=l"(r) : "f"(a), "f"(b)); return r;
}
__device__ __forceinline__ void upk2(float& a, float& b, u64c v) {
    asm("mov.b64 {%0, %1}, %2;" : "=f"(a), "=f"(b) : "l"(v));
}
__device__ __forceinline__ void fma2(u64c& d, u64c a, u64c b) {
    asm("fma.rn.f32x2 %0, %1, %2, %0;" : "+l"(d) : "l"(a), "l"(b));
}

// monotone float<->uint key mapping (larger key <=> larger float)
__device__ __forceinline__ unsigned f2k(float f) {
    unsigned u = __float_as_uint(f);
    return (u & 0x80000000u) ? ~u : (u | 0x80000000u);
}
__device__ __forceinline__ float k2f(unsigned k) {
    unsigned u = (k & 0x80000000u) ? (k ^ 0x80000000u) : ~k;
    return __uint_as_float(u);
}

// ---------------- fp16 hi/lo split of x (lo scaled by 2048) ----------------
__global__ void __launch_bounds__(256) split_kernel(const float4* __restrict__ xsrc) {
    size_t i = (size_t)blockIdx.x * 256 + threadIdx.x;   // grid sized exactly
    __half2* hi = (__half2*)g_xhi;
    __half2* lo = (__half2*)g_xlo;
    float4 v = xsrc[i];
    __half hx = __float2half(v.x), hy = __float2half(v.y);
    __half hz = __float2half(v.z), hw = __float2half(v.w);
    __half2 h0; h0.x = hx; h0.y = hy;
    __half2 h1; h1.x = hz; h1.y = hw;
    __half2 l0, l1;
    l0.x = __float2half((v.x - __half2float(hx)) * LOSCALE);
    l0.y = __float2half((v.y - __half2float(hy)) * LOSCALE);
    l1.x = __float2half((v.z - __half2float(hz)) * LOSCALE);
    l1.y = __float2half((v.w - __half2float(hw)) * LOSCALE);
    hi[2 * i] = h0; hi[2 * i + 1] = h1;
    lo[2 * i] = l0; lo[2 * i + 1] = l1;
}

// ---------------- weight transpose + split: W[k][n] -> Wt[n][k] hi/lo ----------------
__global__ void wsplit_kernel(const float* __restrict__ Wq, const float* __restrict__ Wk,
                              const float* __restrict__ Wv, const float* __restrict__ Wo) {
    int z = blockIdx.z;
    const float* W = (z == 0) ? Wq : (z == 1) ? Wk : (z == 2) ? Wv : Wo;
    __shared__ float t[32][33];
    int n0 = blockIdx.x * 32, k0 = blockIdx.y * 32;
    int tx = threadIdx.x, ty = threadIdx.y;
    t[ty][tx] = W[(size_t)(k0 + ty) * DDIM + n0 + tx];
    __syncthreads();
    float v = t[tx][ty];                      // = W[k0+tx][n0+ty]
    __half h = __float2half(v);
    size_t o = (size_t)z * DDIM * DDIM + (size_t)(n0 + ty) * DDIM + k0 + tx;
    g_wthi[o] = h;
    g_wtlo[o] = __float2half((v - __half2float(h)) * LOSCALE);
}

// ---------------- pv gating MLP: 32 blocks x 8 batches (W1 read 32x less) ----------------
#define PVB 8
__global__ void __launch_bounds__(256) pv_kernel(
    const float* __restrict__ x,
    const float* __restrict__ W1, const float* __restrict__ b1,
    const float* __restrict__ W2, const float* __restrict__ b2)
{
    __shared__ float comb[PVB][1024];
    __shared__ float sred[PVB][257];
    int blk = blockIdx.x;            // 0..31
    int tid = threadIdx.x;
    int b0  = blk * PVB;

    // phase A: price/vol means for 8 batches
    for (int e = tid; e < PVB * 1024; e += 256) {
        int b = e >> 10, i = e & 1023;
        int d = i & 511, hf = i >> 9;
        const float* xb = x + ((size_t)(b0 + b) * FDIM + hf * 64) * DDIM + d;
        float s = 0.f;
#pragma unroll 8
        for (int f = 0; f < 64; f++) s += xb[(size_t)f * DDIM];
        comb[b][i] = s * (1.f / 64.f);
    }
    __syncthreads();

    // phase B: h = silu(comb @ W1 + b1); part = h * W2
    float part[PVB];
#pragma unroll
    for (int b = 0; b < PVB; b++) part[b] = 0.f;

    for (int jj = 0; jj < 2; jj++) {
        int j = tid + jj * 256;
        float acc[PVB];
        float bj = b1[j];
#pragma unroll
        for (int b = 0; b < PVB; b++) acc[b] = bj;
        for (int i = 0; i < 1024; i += 4) {
            float w0 = W1[(size_t)(i + 0) * DDIM + j];
            float w1 = W1[(size_t)(i + 1) * DDIM + j];
            float w2 = W1[(size_t)(i + 2) * DDIM + j];
            float w3 = W1[(size_t)(i + 3) * DDIM + j];
#pragma unroll
            for (int b = 0; b < PVB; b++) {
                float4 c = *(const float4*)&comb[b][i];
                acc[b] += c.x * w0 + c.y * w1 + c.z * w2 + c.w * w3;
            }
        }
        float w2j = W2[j];
#pragma unroll
        for (int b = 0; b < PVB; b++) {
            float h = acc[b] / (1.f + __expf(-acc[b]));   // silu
            part[b] += h * w2j;
        }
    }
#pragma unroll
    for (int b = 0; b < PVB; b++) sred[b][tid] = part[b];
    for (int s = 128; s > 0; s >>= 1) {
        __syncthreads();
        if (tid < s)
#pragma unroll
            for (int b = 0; b < PVB; b++) sred[b][tid] += sred[b][tid + s];
    }
    __syncthreads();
    if (tid < PVB) {
        float z = sred[tid][0] + b2[0];
        g_pv[b0 + tid] = 1.f / (1.f + __expf(-z));
    }
}

// ---------------- HMMA fp16 3-term split GEMM: C[M,512] = A[M,512] @ W + bias ----------------
// Virtual K' = 3*512, K-chunk 64, 3-stage cp.async, 1 sync per 64-K chunk.
//   chunks  0-7  : Ahi *Blo'  \  cross terms at 2^11 scale
//   chunks  8-15 : Alo'*Bhi   /
//   rescale acc *= 2^-11
//   chunks 16-23 : Ahi *Bhi
#define KC      64
#define ROWH    72
#define NCHUNK  24
#define NSTAGE  3
#define TILE_HALF (128 * ROWH)                        // 9216 halves = 18432 B
#define GEMM_SMEM (NSTAGE * TILE_HALF * 2 * 2)        // 110592 bytes

__global__ void __launch_bounds__(256, 2) gemm_mma(
    int mode,
    const float* __restrict__ b0, const float* __restrict__ b1, const float* __restrict__ b2,
    float* __restrict__ Cout)
{
    extern __shared__ __half gsm[];
    uint32_t sAu = smem_u32(gsm);
    uint32_t sBu = smem_u32(gsm + NSTAGE * TILE_HALF);

    int tid  = threadIdx.x;
    int lane = tid & 31;
    int wid  = tid >> 5;
    int wm   = wid & 3;          // 0..3 -> M offset 32*wm
    int wn   = wid >> 2;         // 0..1 -> N offset 64*wn
    int z    = blockIdx.z;

    const __half* Ahi = mode ? g_ahi : g_xhi;
    const __half* Alo = mode ? g_alo : g_xlo;
    int wz = mode ? 3 : z;
    const __half* Bhi = g_wthi + (size_t)wz * DDIM * DDIM;
    const __half* Blo = g_wtlo + (size_t)wz * DDIM * DDIM;
    const float* bias = (z == 0) ? b0 : (z == 1) ? b1 : b2;
    float* C = mode ? Cout : (g_qkv + (size_t)z * MTOT * DDIM);

    int bm = blockIdx.y * 128;
    int bn = blockIdx.x * 128;

    float acc[2][8][4];
#pragma unroll
    for (int mi = 0; mi < 2; mi++)
#pragma unroll
        for (int nj = 0; nj < 8; nj++)
#pragma unroll
            for (int q = 0; q < 4; q++) acc[mi][nj][q] = 0.f;

    // ---- issue loads for one 64-K chunk into buffer `buf` ----
    auto issue = [&](int cc, int buf) {
        int p  = cc >> 3;                      // 0: hi*lo', 1: lo'*hi, 2: hi*hi
        int k0 = (cc & 7) * KC;
        const __half* As = (p == 1) ? Alo : Ahi;
        const __half* Bs = (p == 0) ? Blo : Bhi;
        uint32_t base = (uint32_t)buf * TILE_HALF * 2;
#pragma unroll
        for (int rep = 0; rep < 4; rep++) {
            int idx = rep * 256 + tid;
            int row = idx >> 3, seg = idx & 7;
            uint32_t so = base + (uint32_t)(row * ROWH + seg * 8) * 2;
            cp_async16(sAu + so, As + (size_t)(bm + row) * DDIM + k0 + seg * 8);
            cp_async16(sBu + so, Bs + (size_t)(bn + row) * DDIM + k0 + seg * 8);
        }
        cp_commit();
    };

    issue(0, 0);
    issue(1, 1);
    int cbuf = 0, nbuf = 2;
    for (int cc = 0; cc < NCHUNK; ++cc) {
        cp_wait<1>();
        __syncthreads();
        if (cc + 2 < NCHUNK) issue(cc + 2, nbuf);
        else                 cp_commit();          // keep group count uniform

        uint32_t base = (uint32_t)cbuf * TILE_HALF * 2;
        uint32_t aB = sAu + base, bB = sBu + base;
#pragma unroll
        for (int kk4 = 0; kk4 < 4; kk4++) {      // four k16 groups of the 64-chunk
            uint32_t afr[2][4], bfr[4][4];
            uint32_t colb = (uint32_t)(kk4 * 16 + (lane >> 4) * 8) * 2;
#pragma unroll
            for (int mi = 0; mi < 2; mi++) {
                uint32_t addr = aB + (uint32_t)((wm * 32 + mi * 16 + (lane & 15)) * ROWH) * 2 + colb;
                ldm_x4(afr[mi], addr);
            }
#pragma unroll
            for (int ni = 0; ni < 4; ni++) {
                uint32_t addr = bB + (uint32_t)((wn * 64 + ni * 16 + (lane & 15)) * ROWH) * 2 + colb;
                ldm_x4(bfr[ni], addr);
            }
#pragma unroll
            for (int mi = 0; mi < 2; mi++)
#pragma unroll
                for (int nj = 0; nj < 8; nj++) {
                    int ni = nj >> 1, h2 = nj & 1;
                    mma16816(acc[mi][nj], afr[mi], bfr[ni][h2], bfr[ni][h2 + 2]);
                }
        }
        // undo residual scaling once, after both cross-term passes
        if (cc == 15) {
#pragma unroll
            for (int mi = 0; mi < 2; mi++)
#pragma unroll
                for (int nj = 0; nj < 8; nj++)
#pragma unroll
                    for (int q = 0; q < 4; q++) acc[mi][nj][q] *= INVLOSCALE;
        }
        cbuf = (cbuf + 1 == NSTAGE) ? 0 : cbuf + 1;
        nbuf = (nbuf + 1 == NSTAGE) ? 0 : nbuf + 1;
    }

    // ---- epilogue: direct float2 stores with bias ----
    int rbase = bm + wm * 32 + (lane >> 2);
    int cb    = bn + wn * 64 + 2 * (lane & 3);
#pragma unroll
    for (int mi = 0; mi < 2; mi++) {
#pragma unroll
        for (int nj = 0; nj < 8; nj++) {
            int col = cb + nj * 8;
            float bx = bias[col], by = bias[col + 1];
            float2 v0 = make_float2(acc[mi][nj][0] + bx, acc[mi][nj][1] + by);
            float2 v1 = make_float2(acc[mi][nj][2] + bx, acc[mi][nj][3] + by);
            int r0 = rbase + mi * 16;
            *(float2*)(C + (size_t)r0 * DDIM + col)       = v0;
            *(float2*)(C + (size_t)(r0 + 8) * DDIM + col) = v1;
        }
    }
}

// ---------------- fused attention: one CTA per (b,h) ----------------
// f32x2 packed math; 2-bit radix select; writes hi/lo fp16 split directly.
#define SMEM_ATTN ((128 * 129 + 128 * 64) * 4)

__global__ void __launch_bounds__(128) attn_kernel(
    const float* __restrict__ corr,
    const float* __restrict__ fimp)
{
    extern __shared__ float sm[];
    unsigned* scu = (unsigned*)sm;            // 128*129 keys
    float*    kv  = sm + 128 * 129;           // 128*64 (k tile, then v tile)

    int bh = blockIdx.x;
    int b = bh >> 3, h = bh & 7;
    int r = threadIdx.x;

    const float* qbase = g_qkv + (size_t)b * FDIM * DDIM + h * HD;
    const float* kbase = qbase + (size_t)MTOT * DDIM;
    const float* vbase = qbase + (size_t)2 * MTOT * DDIM;

    // K tile: rows f, head slice (stride DDIM)
    for (int i = r; i < 2048; i += 128) {
        int row = i >> 4, seg = i & 15;
        *(float4*)(kv + row * 64 + seg * 4) =
            *(const float4*)(kbase + (size_t)row * DDIM + seg * 4);
    }
    // q row packed into f32x2 registers
    u64c qv2[32];
    const float4* qp = (const float4*)(qbase + (size_t)r * DDIM);
#pragma unroll
    for (int d = 0; d < 16; d++) {
        float4 t = qp[d];
        qv2[2 * d]     = pk2(t.x, t.y);
        qv2[2 * d + 1] = pk2(t.z, t.w);
    }
    __syncthreads();

    float fi_r = fimp[r];
    float pvh  = g_pv[b] * 0.5f;
    bool  rlo  = (r < 64);
    const float* crow = corr + r * FDIM;
    unsigned* srow = scu + r * 129;

    unsigned kmax = 0u;                       // row max, tracked inline
    for (int j = 0; j < FDIM; j++) {
        const ulonglong2* kp = (const ulonglong2*)(kv + j * HD);
        u64c c0 = 0, c1 = 0, c2 = 0, c3 = 0;
#pragma unroll
        for (int d = 0; d < 16; d += 2) {
            ulonglong2 t0 = kp[d], t1 = kp[d + 1];
            fma2(c0, qv2[2 * d],     t0.x);
            fma2(c1, qv2[2 * d + 1], t0.y);
            fma2(c2, qv2[2 * d + 2], t1.x);
            fma2(c3, qv2[2 * d + 3], t1.y);
        }
        float x0, x1, y0, y1, z0, z1, w0, w1;
        upk2(x0, x1, c0); upk2(y0, y1, c1); upk2(z0, z1, c2); upk2(w0, w1, c3);
        float s = (((x0 + x1) + (y0 + y1)) + ((z0 + z1) + (w0 + w1))) * 0.125f
                + crow[j] * fi_r * fimp[j];
        if (rlo != (j < 64)) s += pvh;
        unsigned key = f2k(s);
        kmax = max(kmax, key);
        srow[j] = key;
    }
    __syncthreads();   // everyone done reading K

    // overwrite kv with V tile
    for (int i = r; i < 2048; i += 128) {
        int row = i >> 4, seg = i & 15;
        *(float4*)(kv + row * 64 + seg * 4) =
            *(const float4*)(vbase + (size_t)row * DDIM + seg * 4);
    }

    // exact 64th-largest via MSB-first 2-bit radix select (16 passes)
    unsigned prefix = 0u;
    int kk = KTOP;
    for (int bit = 30; bit >= 0; bit -= 2) {
        int n3 = 0, n2 = 0, n1 = 0;
        unsigned phi = (prefix >> (bit + 1)) >> 1;   // prefix >> (bit+2), shift-safe
        for (int j = 0; j < FDIM; j++) {
            unsigned key = srow[j];
            bool m = (((key >> (bit + 1)) >> 1) == phi);
            unsigned d = (key >> bit) & 3u;
            n3 += (int)(m && (d == 3u));
            n2 += (int)(m && (d == 2u));
            n1 += (int)(m && (d == 1u));
        }
        if (kk <= n3) prefix |= (3u << bit);
        else {
            kk -= n3;
            if (kk <= n2) prefix |= (2u << bit);
            else {
                kk -= n2;
                if (kk <= n1) prefix |= (1u << bit);
                else kk -= n1;
            }
        }
    }

    float m = k2f(kmax);

    __syncthreads();   // V tile fully loaded

    // single pass: exp + sum + AV accumulate (packed f32x2)
    u64c av[32];
#pragma unroll
    for (int d = 0; d < 32; d++) av[d] = 0ull;
    float ssum = 0.f;
    for (int j = 0; j < FDIM; j++) {
        unsigned key = srow[j];
        float e = (key >= prefix) ? __expf(k2f(key) - m) : 0.f;
        ssum += e;
        u64c e2 = pk2(e, e);
        const ulonglong2* vp = (const ulonglong2*)(kv + j * HD);
#pragma unroll
        for (int d = 0; d < 16; d++) {
            ulonglong2 t = vp[d];
            fma2(av[2 * d],     e2, t.x);
            fma2(av[2 * d + 1], e2, t.y);
        }
    }
    float inv = 1.f / ssum;

    // epilogue: normalize + fp16 hi/lo split, store directly for out-projection
    size_t obase = ((size_t)b * FDIM + r) * DDIM + h * HD;
    __half2* hi2 = (__half2*)(g_ahi + obase);
    __half2* lo2 = (__half2*)(g_alo + obase);
#pragma unroll
    for (int d = 0; d < 32; d++) {
        float a, bb2;
        upk2(a, bb2, av[d]);
        a *= inv; bb2 *= inv;
        __half ha = __float2half(a), hb = __float2half(bb2);
        hi2[d] = __halves2half2(ha, hb);
        lo2[d] = __halves2half2(__float2half((a   - __half2float(ha)) * LOSCALE),
                                __float2half((bb2 - __half2float(hb)) * LOSCALE));
    }
}

// ---------------- launch ----------------
extern "C" void kernel_launch(void* const* d_in, const int* in_sizes, int n_in,
                              void* d_out, int out_size)
{
    const float* x    = (const float*)d_in[0];
    const float* Wq   = (const float*)d_in[1];
    const float* bq   = (const float*)d_in[2];
    const float* Wk   = (const float*)d_in[3];
    const float* bk   = (const float*)d_in[4];
    const float* Wv   = (const float*)d_in[5];
    const float* bv   = (const float*)d_in[6];
    const float* Wo   = (const float*)d_in[7];
    const float* bo   = (const float*)d_in[8];
    const float* corr = (const float*)d_in[9];
    const float* fimp = (const float*)d_in[10];
    const float* W1   = (const float*)d_in[11];
    const float* b1   = (const float*)d_in[12];
    const float* W2   = (const float*)d_in[13];
    const float* b2   = (const float*)d_in[14];
    float* out = (float*)d_out;

    cudaFuncSetAttribute(gemm_mma, cudaFuncAttributeMaxDynamicSharedMemorySize, GEMM_SMEM);
    cudaFuncSetAttribute(attn_kernel, cudaFuncAttributeMaxDynamicSharedMemorySize, SMEM_ATTN);

    // prep: fp16 hi/lo splits of x and transposed weights
    split_kernel<<<16384, 256>>>((const float4*)x);
    wsplit_kernel<<<dim3(16, 16, 4), dim3(32, 32)>>>(Wq, Wk, Wv, Wo);
    pv_kernel<<<32, 256>>>(x, W1, b1, W2, b2);

    // q,k,v projections on tensor cores (HMMA, 3-term split, K64 chunks)
    gemm_mma<<<dim3(4, 256, 3), 256, GEMM_SMEM>>>(0, bq, bk, bv, nullptr);

    // fused sparse attention (writes hi/lo split output directly)
    attn_kernel<<<BSZ * HH, 128, SMEM_ATTN>>>(corr, fimp);

    // output projection on tensor cores
    gemm_mma<<<dim3(4, 256, 1), 256, GEMM_SMEM>>>(1, bo, bo, bo, out);
}

// round 9
// speedup vs baseline: 1.1124x; 1.1124x over previous
#include <cuda_runtime.h>
#include <cuda_fp16.h>
#include <cstdint>

#define BSZ  256
#define FDIM 128
#define DDIM 512
#define HH   8
#define HD   64
#define KTOP 64
#define MTOT (BSZ * FDIM)            // 32768
#define LOSCALE 2048.0f
#define INVLOSCALE (1.0f / 2048.0f)

// ---------------- scratch (device globals: allocation-free) ----------------
__device__ float g_qkv[(size_t)3 * MTOT * DDIM];   // q,k,v in (B,F,D) plain layout
__device__ float g_pv[BSZ];
__device__ __half g_xhi[(size_t)MTOT * DDIM];
__device__ __half g_xlo[(size_t)MTOT * DDIM];      // scaled by 2048
__device__ __half g_ahi[(size_t)MTOT * DDIM];      // attn out hi (written by attn_kernel)
__device__ __half g_alo[(size_t)MTOT * DDIM];      // attn out lo (scaled by 2048)
__device__ __half g_wthi[(size_t)4 * DDIM * DDIM]; // W^T (n,k) for q,k,v,o
__device__ __half g_wtlo[(size_t)4 * DDIM * DDIM]; // scaled by 2048

// ---------------- helpers ----------------
typedef unsigned long long u64c;

__device__ __forceinline__ uint32_t smem_u32(const void* p) {
    uint32_t a;
    asm("{ .reg .u64 t; cvta.to.shared.u64 t, %1; cvt.u32.u64 %0, t; }" : "=r"(a) : "l"(p));
    return a;
}
__device__ __forceinline__ void cp_async16(uint32_t dst, const void* src) {
    asm volatile("cp.async.cg.shared.global [%0], [%1], 16;" :: "r"(dst), "l"(src) : "memory");
}
__device__ __forceinline__ void cp_commit() {
    asm volatile("cp.async.commit_group;" ::: "memory");
}
template<int N>
__device__ __forceinline__ void cp_wait() {
    asm volatile("cp.async.wait_group %0;" :: "n"(N) : "memory");
}
__device__ __forceinline__ void ldm_x4(uint32_t* r, uint32_t addr) {
    asm volatile("ldmatrix.sync.aligned.m8n8.x4.shared.b16 {%0,%1,%2,%3}, [%4];"
                 : "=r"(r[0]), "=r"(r[1]), "=r"(r[2]), "=r"(r[3]) : "r"(addr));
}
__device__ __forceinline__ void mma16816(float* c, const uint32_t* a, uint32_t b0, uint32_t b1) {
    asm volatile(
        "mma.sync.aligned.m16n8k16.row.col.f32.f16.f16.f32 "
        "{%0,%1,%2,%3}, {%4,%5,%6,%7}, {%8,%9}, {%0,%1,%2,%3};"
        : "+f"(c[0]), "+f"(c[1]), "+f"(c[2]), "+f"(c[3])
        : "r"(a[0]), "r"(a[1]), "r"(a[2]), "r"(a[3]), "r"(b0), "r"(b1));
}
// packed f32x2 ops (sm_100+ base ISA)
__device__ __forceinline__ u64c pk2(float a, float b) {
    u64c r; asm("mov.b64 %0, {%1, %2};" : "=l"(r) : "f"(a), "f"(b)); return r;
}
__device__ __forceinline__ void upk2(float& a, float& b, u64c v) {
    asm("mov.b64 {%0, %1}, %2;" : "=f"(a), "=f"(b) : "l"(v));
}
__device__ __forceinline__ void fma2(u64c& d, u64c a, u64c b) {
    asm("fma.rn.f32x2 %0, %1, %2, %0;" : "+l"(d) : "l"(a), "l"(b));
}

// monotone float<->uint key mapping (larger key <=> larger float)
__device__ __forceinline__ unsigned f2k(float f) {
    unsigned u = __float_as_uint(f);
    return (u & 0x80000000u) ? ~u : (u | 0x80000000u);
}
__device__ __forceinline__ float k2f(unsigned k) {
    unsigned u = (k & 0x80000000u) ? (k ^ 0x80000000u) : ~k;
    return __uint_as_float(u);
}

// ---------------- fp16 hi/lo split of x (lo scaled by 2048) ----------------
__global__ void __launch_bounds__(256) split_kernel(const float4* __restrict__ xsrc) {
    size_t i = (size_t)blockIdx.x * 256 + threadIdx.x;   // grid sized exactly
    __half2* hi = (__half2*)g_xhi;
    __half2* lo = (__half2*)g_xlo;
    float4 v = xsrc[i];
    __half hx = __float2half(v.x), hy = __float2half(v.y);
    __half hz = __float2half(v.z), hw = __float2half(v.w);
    __half2 h0; h0.x = hx; h0.y = hy;
    __half2 h1; h1.x = hz; h1.y = hw;
    __half2 l0, l1;
    l0.x = __float2half((v.x - __half2float(hx)) * LOSCALE);
    l0.y = __float2half((v.y - __half2float(hy)) * LOSCALE);
    l1.x = __float2half((v.z - __half2float(hz)) * LOSCALE);
    l1.y = __float2half((v.w - __half2float(hw)) * LOSCALE);
    hi[2 * i] = h0; hi[2 * i + 1] = h1;
    lo[2 * i] = l0; lo[2 * i + 1] = l1;
}

// ---------------- weight transpose + split: W[k][n] -> Wt[n][k] hi/lo ----------------
__global__ void wsplit_kernel(const float* __restrict__ Wq, const float* __restrict__ Wk,
                              const float* __restrict__ Wv, const float* __restrict__ Wo) {
    int z = blockIdx.z;
    const float* W = (z == 0) ? Wq : (z == 1) ? Wk : (z == 2) ? Wv : Wo;
    __shared__ float t[32][33];
    int n0 = blockIdx.x * 32, k0 = blockIdx.y * 32;
    int tx = threadIdx.x, ty = threadIdx.y;
    t[ty][tx] = W[(size_t)(k0 + ty) * DDIM + n0 + tx];
    __syncthreads();
    float v = t[tx][ty];                      // = W[k0+tx][n0+ty]
    __half h = __float2half(v);
    size_t o = (size_t)z * DDIM * DDIM + (size_t)(n0 + ty) * DDIM + k0 + tx;
    g_wthi[o] = h;
    g_wtlo[o] = __float2half((v - __half2float(h)) * LOSCALE);
}

// ---------------- pv gating MLP: one block per batch (R7 version) ----------------
__global__ void __launch_bounds__(256) pv_kernel(
    const float* __restrict__ x,
    const float* __restrict__ W1, const float* __restrict__ b1,
    const float* __restrict__ W2, const float* __restrict__ b2)
{
    int b = blockIdx.x;
    int tid = threadIdx.x;
    __shared__ float comb[1024];
    __shared__ float red[256];

    for (int d = tid; d < DDIM; d += 256) {
        float s1 = 0.f, s2 = 0.f;
        const float* xb = x + (size_t)b * FDIM * DDIM;
        for (int f = 0; f < 64; f++)   s1 += xb[f * DDIM + d];
        for (int f = 64; f < 128; f++) s2 += xb[f * DDIM + d];
        comb[d]       = s1 * (1.f / 64.f);
        comb[512 + d] = s2 * (1.f / 64.f);
    }
    __syncthreads();

    float part = 0.f;
    for (int j = tid; j < DDIM; j += 256) {
        float acc = b1[j];
        for (int i = 0; i < 1024; i++) acc += comb[i] * W1[i * DDIM + j];
        float hsil = acc / (1.f + __expf(-acc));
        part += hsil * W2[j];
    }
    red[tid] = part;
    for (int s = 128; s > 0; s >>= 1) {
        __syncthreads();
        if (tid < s) red[tid] += red[tid + s];
    }
    __syncthreads();
    if (tid == 0) {
        float z = red[0] + b2[0];
        g_pv[b] = 1.f / (1.f + __expf(-z));
    }
}

// ---------------- HMMA fp16 3-term split GEMM: C[M,512] = A[M,512] @ W + bias ----------------
// Virtual K' = 3*512, K-chunk 64, 3-stage cp.async, 1 sync per 64-K chunk.
//   chunks  0-7  : Ahi *Blo'  \  cross terms at 2^11 scale
//   chunks  8-15 : Alo'*Bhi   /
//   rescale acc *= 2^-11
//   chunks 16-23 : Ahi *Bhi
#define KC      64
#define ROWH    72
#define NCHUNK  24
#define NSTAGE  3
#define TILE_HALF (128 * ROWH)                        // 9216 halves = 18432 B
#define GEMM_SMEM (NSTAGE * TILE_HALF * 2 * 2)        // 110592 bytes

__global__ void __launch_bounds__(256, 2) gemm_mma(
    int mode,
    const float* __restrict__ b0, const float* __restrict__ b1, const float* __restrict__ b2,
    float* __restrict__ Cout)
{
    extern __shared__ __half gsm[];
    uint32_t sAu = smem_u32(gsm);
    uint32_t sBu = smem_u32(gsm + NSTAGE * TILE_HALF);

    int tid  = threadIdx.x;
    int lane = tid & 31;
    int wid  = tid >> 5;
    int wm   = wid & 3;          // 0..3 -> M offset 32*wm
    int wn   = wid >> 2;         // 0..1 -> N offset 64*wn
    int z    = blockIdx.z;

    const __half* Ahi = mode ? g_ahi : g_xhi;
    const __half* Alo = mode ? g_alo : g_xlo;
    int wz = mode ? 3 : z;
    const __half* Bhi = g_wthi + (size_t)wz * DDIM * DDIM;
    const __half* Blo = g_wtlo + (size_t)wz * DDIM * DDIM;
    const float* bias = (z == 0) ? b0 : (z == 1) ? b1 : b2;
    float* C = mode ? Cout : (g_qkv + (size_t)z * MTOT * DDIM);

    int bm = blockIdx.y * 128;
    int bn = blockIdx.x * 128;

    float acc[2][8][4];
#pragma unroll
    for (int mi = 0; mi < 2; mi++)
#pragma unroll
        for (int nj = 0; nj < 8; nj++)
#pragma unroll
            for (int q = 0; q < 4; q++) acc[mi][nj][q] = 0.f;

    // ---- issue loads for one 64-K chunk into buffer `buf` ----
    auto issue = [&](int cc, int buf) {
        int p  = cc >> 3;                      // 0: hi*lo', 1: lo'*hi, 2: hi*hi
        int k0 = (cc & 7) * KC;
        const __half* As = (p == 1) ? Alo : Ahi;
        const __half* Bs = (p == 0) ? Blo : Bhi;
        uint32_t base = (uint32_t)buf * TILE_HALF * 2;
#pragma unroll
        for (int rep = 0; rep < 4; rep++) {
            int idx = rep * 256 + tid;
            int row = idx >> 3, seg = idx & 7;
            uint32_t so = base + (uint32_t)(row * ROWH + seg * 8) * 2;
            cp_async16(sAu + so, As + (size_t)(bm + row) * DDIM + k0 + seg * 8);
            cp_async16(sBu + so, Bs + (size_t)(bn + row) * DDIM + k0 + seg * 8);
        }
        cp_commit();
    };

    issue(0, 0);
    issue(1, 1);
    int cbuf = 0, nbuf = 2;
    for (int cc = 0; cc < NCHUNK; ++cc) {
        cp_wait<1>();
        __syncthreads();
        if (cc + 2 < NCHUNK) issue(cc + 2, nbuf);
        else                 cp_commit();          // keep group count uniform

        uint32_t base = (uint32_t)cbuf * TILE_HALF * 2;
        uint32_t aB = sAu + base, bB = sBu + base;
#pragma unroll
        for (int kk4 = 0; kk4 < 4; kk4++) {      // four k16 groups of the 64-chunk
            uint32_t afr[2][4], bfr[4][4];
            uint32_t colb = (uint32_t)(kk4 * 16 + (lane >> 4) * 8) * 2;
#pragma unroll
            for (int mi = 0; mi < 2; mi++) {
                uint32_t addr = aB + (uint32_t)((wm * 32 + mi * 16 + (lane & 15)) * ROWH) * 2 + colb;
                ldm_x4(afr[mi], addr);
            }
#pragma unroll
            for (int ni = 0; ni < 4; ni++) {
                uint32_t addr = bB + (uint32_t)((wn * 64 + ni * 16 + (lane & 15)) * ROWH) * 2 + colb;
                ldm_x4(bfr[ni], addr);
            }
#pragma unroll
            for (int mi = 0; mi < 2; mi++)
#pragma unroll
                for (int nj = 0; nj < 8; nj++) {
                    int ni = nj >> 1, h2 = nj & 1;
                    mma16816(acc[mi][nj], afr[mi], bfr[ni][h2], bfr[ni][h2 + 2]);
                }
        }
        // undo residual scaling once, after both cross-term passes
        if (cc == 15) {
#pragma unroll
            for (int mi = 0; mi < 2; mi++)
#pragma unroll
                for (int nj = 0; nj < 8; nj++)
#pragma unroll
                    for (int q = 0; q < 4; q++) acc[mi][nj][q] *= INVLOSCALE;
        }
        cbuf = (cbuf + 1 == NSTAGE) ? 0 : cbuf + 1;
        nbuf = (nbuf + 1 == NSTAGE) ? 0 : nbuf + 1;
    }

    // ---- epilogue: direct float2 stores with bias ----
    int rbase = bm + wm * 32 + (lane >> 2);
    int cb    = bn + wn * 64 + 2 * (lane & 3);
#pragma unroll
    for (int mi = 0; mi < 2; mi++) {
#pragma unroll
        for (int nj = 0; nj < 8; nj++) {
            int col = cb + nj * 8;
            float bx = bias[col], by = bias[col + 1];
            float2 v0 = make_float2(acc[mi][nj][0] + bx, acc[mi][nj][1] + by);
            float2 v1 = make_float2(acc[mi][nj][2] + bx, acc[mi][nj][3] + by);
            int r0 = rbase + mi * 16;
            *(float2*)(C + (size_t)r0 * DDIM + col)       = v0;
            *(float2*)(C + (size_t)(r0 + 8) * DDIM + col) = v1;
        }
    }
}

// ---------------- fused attention: one CTA per (b,h) ----------------
// f32x2 packed math; 1-bit radix select (R7); inline row-max; fp16 hi/lo output.
#define SMEM_ATTN ((128 * 129 + 128 * 64) * 4)

__global__ void __launch_bounds__(128) attn_kernel(
    const float* __restrict__ corr,
    const float* __restrict__ fimp)
{
    extern __shared__ float sm[];
    unsigned* scu = (unsigned*)sm;            // 128*129 keys
    float*    kv  = sm + 128 * 129;           // 128*64 (k tile, then v tile)

    int bh = blockIdx.x;
    int b = bh >> 3, h = bh & 7;
    int r = threadIdx.x;

    const float* qbase = g_qkv + (size_t)b * FDIM * DDIM + h * HD;
    const float* kbase = qbase + (size_t)MTOT * DDIM;
    const float* vbase = qbase + (size_t)2 * MTOT * DDIM;

    // K tile: rows f, head slice (stride DDIM)
    for (int i = r; i < 2048; i += 128) {
        int row = i >> 4, seg = i & 15;
        *(float4*)(kv + row * 64 + seg * 4) =
            *(const float4*)(kbase + (size_t)row * DDIM + seg * 4);
    }
    // q row packed into f32x2 registers
    u64c qv2[32];
    const float4* qp = (const float4*)(qbase + (size_t)r * DDIM);
#pragma unroll
    for (int d = 0; d < 16; d++) {
        float4 t = qp[d];
        qv2[2 * d]     = pk2(t.x, t.y);
        qv2[2 * d + 1] = pk2(t.z, t.w);
    }
    __syncthreads();

    float fi_r = fimp[r];
    float pvh  = g_pv[b] * 0.5f;
    bool  rlo  = (r < 64);
    const float* crow = corr + r * FDIM;
    unsigned* srow = scu + r * 129;

    unsigned kmax = 0u;                       // row max, tracked inline
    for (int j = 0; j < FDIM; j++) {
        const ulonglong2* kp = (const ulonglong2*)(kv + j * HD);
        u64c c0 = 0, c1 = 0, c2 = 0, c3 = 0;
#pragma unroll
        for (int d = 0; d < 16; d += 2) {
            ulonglong2 t0 = kp[d], t1 = kp[d + 1];
            fma2(c0, qv2[2 * d],     t0.x);
            fma2(c1, qv2[2 * d + 1], t0.y);
            fma2(c2, qv2[2 * d + 2], t1.x);
            fma2(c3, qv2[2 * d + 3], t1.y);
        }
        float x0, x1, y0, y1, z0, z1, w0, w1;
        upk2(x0, x1, c0); upk2(y0, y1, c1); upk2(z0, z1, c2); upk2(w0, w1, c3);
        float s = (((x0 + x1) + (y0 + y1)) + ((z0 + z1) + (w0 + w1))) * 0.125f
                + crow[j] * fi_r * fimp[j];
        if (rlo != (j < 64)) s += pvh;
        unsigned key = f2k(s);
        kmax = max(kmax, key);
        srow[j] = key;
    }
    __syncthreads();   // everyone done reading K

    // overwrite kv with V tile
    for (int i = r; i < 2048; i += 128) {
        int row = i >> 4, seg = i & 15;
        *(float4*)(kv + row * 64 + seg * 4) =
            *(const float4*)(vbase + (size_t)row * DDIM + seg * 4);
    }

    // exact 64th-largest via MSB-first 1-bit radix select (R7)
    unsigned prefix = 0u;
    int kk = KTOP;
    for (int bit = 31; bit >= 0; --bit) {
        unsigned want = (prefix >> bit) | 1u;
        int c = 0;
#pragma unroll 4
        for (int j = 0; j < FDIM; j++) c += (int)((srow[j] >> bit) == want);
        if (c >= kk) prefix |= (1u << bit); else kk -= c;
    }

    float m = k2f(kmax);

    __syncthreads();   // V tile fully loaded

    // single pass: exp + sum + AV accumulate (packed f32x2)
    u64c av[32];
#pragma unroll
    for (int d = 0; d < 32; d++) av[d] = 0ull;
    float ssum = 0.f;
    for (int j = 0; j < FDIM; j++) {
        unsigned key = srow[j];
        float e = (key >= prefix) ? __expf(k2f(key) - m) : 0.f;
        ssum += e;
        u64c e2 = pk2(e, e);
        const ulonglong2* vp = (const ulonglong2*)(kv + j * HD);
#pragma unroll
        for (int d = 0; d < 16; d++) {
            ulonglong2 t = vp[d];
            fma2(av[2 * d],     e2, t.x);
            fma2(av[2 * d + 1], e2, t.y);
        }
    }
    float inv = 1.f / ssum;

    // epilogue: normalize + fp16 hi/lo split, store directly for out-projection
    size_t obase = ((size_t)b * FDIM + r) * DDIM + h * HD;
    __half2* hi2 = (__half2*)(g_ahi + obase);
    __half2* lo2 = (__half2*)(g_alo + obase);
#pragma unroll
    for (int d = 0; d < 32; d++) {
        float a, bb2;
        upk2(a, bb2, av[d]);
        a *= inv; bb2 *= inv;
        __half ha = __float2half(a), hb = __float2half(bb2);
        hi2[d] = __halves2half2(ha, hb);
        lo2[d] = __halves2half2(__float2half((a   - __half2float(ha)) * LOSCALE),
                                __float2half((bb2 - __half2float(hb)) * LOSCALE));
    }
}

// ---------------- launch ----------------
extern "C" void kernel_launch(void* const* d_in, const int* in_sizes, int n_in,
                              void* d_out, int out_size)
{
    const float* x    = (const float*)d_in[0];
    const float* Wq   = (const float*)d_in[1];
    const float* bq   = (const float*)d_in[2];
    const float* Wk   = (const float*)d_in[3];
    const float* bk   = (const float*)d_in[4];
    const float* Wv   = (const float*)d_in[5];
    const float* bv   = (const float*)d_in[6];
    const float* Wo   = (const float*)d_in[7];
    const float* bo   = (const float*)d_in[8];
    const float* corr = (const float*)d_in[9];
    const float* fimp = (const float*)d_in[10];
    const float* W1   = (const float*)d_in[11];
    const float* b1   = (const float*)d_in[12];
    const float* W2   = (const float*)d_in[13];
    const float* b2   = (const float*)d_in[14];
    float* out = (float*)d_out;

    cudaFuncSetAttribute(gemm_mma, cudaFuncAttributeMaxDynamicSharedMemorySize, GEMM_SMEM);
    cudaFuncSetAttribute(attn_kernel, cudaFuncAttributeMaxDynamicSharedMemorySize, SMEM_ATTN);

    // prep: fp16 hi/lo splits of x and transposed weights
    split_kernel<<<16384, 256>>>((const float4*)x);
    wsplit_kernel<<<dim3(16, 16, 4), dim3(32, 32)>>>(Wq, Wk, Wv, Wo);
    pv_kernel<<<BSZ, 256>>>(x, W1, b1, W2, b2);

    // q,k,v projections on tensor cores (HMMA, 3-term split, K64 chunks)
    gemm_mma<<<dim3(4, 256, 3), 256, GEMM_SMEM>>>(0, bq, bk, bv, nullptr);

    // fused sparse attention (writes hi/lo split output directly)
    attn_kernel<<<BSZ * HH, 128, SMEM_ATTN>>>(corr, fimp);

    // output projection on tensor cores
    gemm_mma<<<dim3(4, 256, 1), 256, GEMM_SMEM>>>(1, bo, bo, bo, out);
}